// round 4
// baseline (speedup 1.0000x reference)
#include <cuda_runtime.h>
#include <cuda_bf16.h>

// 4-qubit circuit, algebraically collapsed:
//   embedded state v = kron of per-wire (cos,sin)  (real, rank-1 over wire pairs)
//   entangling block = fixed 16x16 complex unitary U (weights only)
//   z_w = sign-tree over |U v|^2
//
// R4: NB=1 + launch_bounds(128,6) to raise occupancy (R3 was reg-bound at
// occ=20%, issue=44%); U read from smem as ulonglong2 so the LDS.128 result
// pair feeds fma.rn.f32x2 directly (no pack MOVs); v built on the fly from
// P[4]xQ[4] factors.

#define N_QUBITS 4
#define N_LAYERS 6
#define N_AMPS   16
#define THREADS  128
#define U_F4     128        // 16x16 complex = 256 float2 = 128 x 16B slots

__device__ float4 g_U[U_F4];   // col i: slots [i*8, i*8+8); slot j = (U[2j][i], U[2j+1][i])

__device__ __forceinline__ void apply_gate(float2* s, int wire,
                                           float2 u00, float2 u01,
                                           float2 u10, float2 u11) {
    const int stride = 8 >> wire;    // wire 0 is MSB of the amplitude index
    #pragma unroll
    for (int i = 0; i < N_AMPS; i++) {
        if (i & stride) continue;
        float2 a0 = s[i];
        float2 a1 = s[i + stride];
        float2 n0, n1;
        n0.x = u00.x * a0.x - u00.y * a0.y + u01.x * a1.x - u01.y * a1.y;
        n0.y = u00.x * a0.y + u00.y * a0.x + u01.x * a1.y + u01.y * a1.x;
        n1.x = u10.x * a0.x - u10.y * a0.y + u11.x * a1.x - u11.y * a1.y;
        n1.y = u10.x * a0.y + u10.y * a0.x + u11.x * a1.y + u11.y * a1.x;
        s[i]          = n0;
        s[i + stride] = n1;
    }
}

__global__ void init_u_kernel(const float* __restrict__ w) {
    int i = threadIdx.x;             // basis column index
    if (i >= N_AMPS) return;
    float2 s[N_AMPS];
    #pragma unroll
    for (int j = 0; j < N_AMPS; j++)
        s[j] = make_float2(j == i ? 1.0f : 0.0f, 0.0f);

    #pragma unroll
    for (int l = 0; l < N_LAYERS; l++) {
        #pragma unroll
        for (int q = 0; q < N_QUBITS; q++) {
            int idx = l * N_QUBITS + q;
            float phi   = w[idx * 3 + 0];
            float theta = w[idx * 3 + 1];
            float omega = w[idx * 3 + 2];
            float st, ct, sp, cp, sm, cm;
            __sincosf(theta * 0.5f, &st, &ct);
            __sincosf((phi + omega) * 0.5f, &sp, &cp);
            __sincosf((phi - omega) * 0.5f, &sm, &cm);
            float2 u00 = make_float2( cp * ct, -sp * ct);
            float2 u01 = make_float2(-cm * st, -sm * st);
            float2 u10 = make_float2( cm * st, -sm * st);
            float2 u11 = make_float2( cp * ct,  sp * ct);
            apply_gate(s, q, u00, u01, u10, u11);
        }
        const int r = l % (N_QUBITS - 1) + 1;
        #pragma unroll
        for (int q = 0; q < N_QUBITS; q++) {
            const int cbit = 8 >> q, tbit = 8 >> ((q + r) % N_QUBITS);
            #pragma unroll
            for (int a = 0; a < N_AMPS; a++) {
                if ((a & cbit) && !(a & tbit)) {
                    float2 t = s[a]; s[a] = s[a + tbit]; s[a + tbit] = t;
                }
            }
        }
    }
    float2* U = reinterpret_cast<float2*>(g_U);
    #pragma unroll
    for (int m = 0; m < N_AMPS; m++)
        U[i * N_AMPS + m] = s[m];    // column i contiguous
}

__device__ __forceinline__ unsigned long long pack2(float lo, float hi) {
    unsigned long long r;
    asm("mov.b64 %0, {%1, %2};" : "=l"(r) : "f"(lo), "f"(hi));
    return r;
}

// readout: z_w = sign-tree over p[m] = |y[m]|^2
__device__ __forceinline__ float4 readout(const unsigned long long* y) {
    float p[N_AMPS];
    #pragma unroll
    for (int m = 0; m < N_AMPS; m++) {
        float re, im;
        asm("mov.b64 {%0, %1}, %2;" : "=f"(re), "=f"(im) : "l"(y[m]));
        p[m] = re * re + im * im;
    }
    float a0 = p[0]  + p[1],  a1 = p[2]  + p[3],  a2 = p[4]  + p[5],  a3 = p[6]  + p[7];
    float a4 = p[8]  + p[9],  a5 = p[10] + p[11], a6 = p[12] + p[13], a7 = p[14] + p[15];
    float z3 = ((p[0] - p[1]) + (p[2] - p[3])) + ((p[4] - p[5]) + (p[6] - p[7]))
             + ((p[8] - p[9]) + (p[10] - p[11])) + ((p[12] - p[13]) + (p[14] - p[15]));
    float b0 = a0 + a1, b1 = a2 + a3, b2 = a4 + a5, b3 = a6 + a7;
    float z2 = ((a0 - a1) + (a2 - a3)) + ((a4 - a5) + (a6 - a7));
    float z1 = (b0 - b1) + (b2 - b3);
    float z0 = (b0 + b1) - (b2 + b3);
    return make_float4(z0, z1, z2, z3);
}

__global__ void __launch_bounds__(THREADS, 6)
quantum_main_kernel(const float* __restrict__ inputs,
                    float* __restrict__ out, int B) {
    __shared__ float4 sU[U_F4];
    if (threadIdx.x < U_F4) sU[threadIdx.x] = g_U[threadIdx.x];
    __syncthreads();
    const ulonglong2* sU2 = reinterpret_cast<const ulonglong2*>(sU);

    const int b = blockIdx.x * THREADS + threadIdx.x;
    if (b >= B) return;

    // ---- embedding factors: v[i] = P[i>>2] * Q[i&3] ----
    float4 x = __ldg(reinterpret_cast<const float4*>(inputs) + b);
    float c0, s0, c1, s1, c2, s2, c3, s3;
    __sincosf(x.x * 0.5f, &s0, &c0);
    __sincosf(x.y * 0.5f, &s1, &c1);
    __sincosf(x.z * 0.5f, &s2, &c2);
    __sincosf(x.w * 0.5f, &s3, &c3);
    float P[4] = {c0 * c1, c0 * s1, s0 * c1, s0 * s1};
    float Q[4] = {c2 * c3, c2 * s3, s2 * c3, s2 * s3};

    unsigned long long y[N_AMPS];
    #pragma unroll
    for (int m = 0; m < N_AMPS; m++) y[m] = 0ull;

    // ---- y = U v, packed (re,im) FFMA2, U broadcast from smem ----
    #pragma unroll
    for (int i = 0; i < N_AMPS; i++) {
        float v = P[i >> 2] * Q[i & 3];
        unsigned long long vp = pack2(v, v);
        #pragma unroll
        for (int j = 0; j < 8; j++) {
            ulonglong2 uu = sU2[i * 8 + j];     // (U[2j][i], U[2j+1][i]) as u64 pairs
            asm("fma.rn.f32x2 %0, %1, %2, %0;" : "+l"(y[2*j    ]) : "l"(uu.x), "l"(vp));
            asm("fma.rn.f32x2 %0, %1, %2, %0;" : "+l"(y[2*j + 1]) : "l"(uu.y), "l"(vp));
        }
    }

    reinterpret_cast<float4*>(out)[b] = readout(y);
}

extern "C" void kernel_launch(void* const* d_in, const int* in_sizes, int n_in,
                              void* d_out, int out_size) {
    const float* inputs  = (const float*)d_in[0];   // (B, 4) float32
    const float* weights = (const float*)d_in[1];   // (6, 4, 3) float32
    float* out = (float*)d_out;                     // (B, 4) float32
    int B = in_sizes[0] / N_QUBITS;

    init_u_kernel<<<1, 32>>>(weights);
    int blocks = (B + THREADS - 1) / THREADS;
    quantum_main_kernel<<<blocks, THREADS>>>(inputs, out, B);
}

// round 5
// speedup vs baseline: 1.4076x; 1.4076x over previous
#include <cuda_runtime.h>
#include <cuda_bf16.h>

// 4-qubit circuit, algebraically collapsed:
//   embedded state v = kron of per-wire (cos,sin)  (real, rank-1 per wire-pair)
//   entangling block = fixed 16x16 complex unitary U (weights only)
//   z_w = sign-tree over |U v|^2
//
// R5: (1) NB=2 to halve LDS/sample (R4 regression root cause: LDS crossbar
// floor), with P/Q on-the-fly + ulonglong2 smem loads to stay <=102 regs at
// 5 blocks/SM. (2) Parallel shfl-based init kernel (8 warps x 2 columns,
// one amplitude per lane) replacing the ~6us serial 1-warp init.

#define N_QUBITS 4
#define N_LAYERS 6
#define N_AMPS   16
#define THREADS  128
#define U_F4     128        // 16x16 complex = 256 float2 = 128 x 16B slots

__device__ float4 g_U[U_F4];   // col i: float2 slots [i*16, i*16+16); m-th = U[m][i]

// ---------------- init: evolve 16 basis columns, shfl pair-exchange ----------------
__global__ void init_u_kernel(const float* __restrict__ w) {
    // gate matrices: [24][2] float4 = (u00,u01),(u10,u11)
    __shared__ float4 gm[N_LAYERS * N_QUBITS][2];
    int t = threadIdx.x;
    if (t < N_LAYERS * N_QUBITS) {
        float phi   = w[t * 3 + 0];
        float theta = w[t * 3 + 1];
        float omega = w[t * 3 + 2];
        float st, ct, sp, cp, sm, cm;
        __sincosf(theta * 0.5f, &st, &ct);
        __sincosf((phi + omega) * 0.5f, &sp, &cp);
        __sincosf((phi - omega) * 0.5f, &sm, &cm);
        gm[t][0] = make_float4( cp * ct, -sp * ct,   // u00
                               -cm * st, -sm * st);  // u01
        gm[t][1] = make_float4( cm * st, -sm * st,   // u10
                                cp * ct,  sp * ct);  // u11
    }
    __syncthreads();

    // 256 threads = 8 warps; each warp evolves 2 columns (16 lanes each).
    int lane   = t & 31;
    int lane16 = lane & 15;                 // amplitude index m
    int col    = (t >> 5) * 2 + (lane >> 4);
    float re = (lane16 == col) ? 1.0f : 0.0f;
    float im = 0.0f;

    #pragma unroll
    for (int l = 0; l < N_LAYERS; l++) {
        #pragma unroll
        for (int q = 0; q < N_QUBITS; q++) {
            int idx = l * N_QUBITS + q;
            float4 row0 = gm[idx][0];       // u00, u01
            float4 row1 = gm[idx][1];       // u10, u11
            const int stride = 8 >> q;
            int bit = lane16 & stride;
            float pre = __shfl_xor_sync(0xffffffffu, re, stride);
            float pim = __shfl_xor_sync(0xffffffffu, im, stride);
            // bit=0: n = u00*own + u01*partner ; bit=1: n = u10*partner + u11*own
            float c0r = bit ? row1.x : row0.x,  c0i = bit ? row1.y : row0.y;
            float c1r = bit ? row1.z : row0.z,  c1i = bit ? row1.w : row0.w;
            float a0r = bit ? pre : re,  a0i = bit ? pim : im;
            float a1r = bit ? re : pre,  a1i = bit ? im : pim;
            float nre = c0r * a0r - c0i * a0i + c1r * a1r - c1i * a1i;
            float nim = c0r * a0i + c0i * a0r + c1r * a1i + c1i * a1r;
            re = nre; im = nim;
        }
        const int r = l % (N_QUBITS - 1) + 1;
        #pragma unroll
        for (int q = 0; q < N_QUBITS; q++) {
            const int cbit = 8 >> q, tbit = 8 >> ((q + r) % N_QUBITS);
            float pre = __shfl_xor_sync(0xffffffffu, re, tbit);
            float pim = __shfl_xor_sync(0xffffffffu, im, tbit);
            bool flip = (lane16 & cbit) != 0;
            re = flip ? pre : re;
            im = flip ? pim : im;
        }
    }
    float2* U = reinterpret_cast<float2*>(g_U);
    U[col * N_AMPS + lane16] = make_float2(re, im);
}

// ---------------- main ----------------
__device__ __forceinline__ unsigned long long pack2(float lo, float hi) {
    unsigned long long r;
    asm("mov.b64 %0, {%1, %2};" : "=l"(r) : "f"(lo), "f"(hi));
    return r;
}

__device__ __forceinline__ float4 readout(const unsigned long long* y) {
    float p[N_AMPS];
    #pragma unroll
    for (int m = 0; m < N_AMPS; m++) {
        float re, im;
        asm("mov.b64 {%0, %1}, %2;" : "=f"(re), "=f"(im) : "l"(y[m]));
        p[m] = re * re + im * im;
    }
    float a0 = p[0]  + p[1],  a1 = p[2]  + p[3],  a2 = p[4]  + p[5],  a3 = p[6]  + p[7];
    float a4 = p[8]  + p[9],  a5 = p[10] + p[11], a6 = p[12] + p[13], a7 = p[14] + p[15];
    float z3 = ((p[0] - p[1]) + (p[2] - p[3])) + ((p[4] - p[5]) + (p[6] - p[7]))
             + ((p[8] - p[9]) + (p[10] - p[11])) + ((p[12] - p[13]) + (p[14] - p[15]));
    float b0 = a0 + a1, b1 = a2 + a3, b2 = a4 + a5, b3 = a6 + a7;
    float z2 = ((a0 - a1) + (a2 - a3)) + ((a4 - a5) + (a6 - a7));
    float z1 = (b0 - b1) + (b2 - b3);
    float z0 = (b0 + b1) - (b2 + b3);
    return make_float4(z0, z1, z2, z3);
}

__device__ __forceinline__ void embed_pq(const float4 x, float* P, float* Q) {
    float c0, s0, c1, s1, c2, s2, c3, s3;
    __sincosf(x.x * 0.5f, &s0, &c0);
    __sincosf(x.y * 0.5f, &s1, &c1);
    __sincosf(x.z * 0.5f, &s2, &c2);
    __sincosf(x.w * 0.5f, &s3, &c3);
    P[0] = c0 * c1; P[1] = c0 * s1; P[2] = s0 * c1; P[3] = s0 * s1;
    Q[0] = c2 * c3; Q[1] = c2 * s3; Q[2] = s2 * c3; Q[3] = s2 * s3;
}

__global__ void __launch_bounds__(THREADS, 5)
quantum_main_kernel(const float* __restrict__ inputs,
                    float* __restrict__ out, int B) {
    __shared__ float4 sU[U_F4];
    sU[threadIdx.x] = g_U[threadIdx.x];     // THREADS == U_F4
    __syncthreads();
    const ulonglong2* sU2 = reinterpret_cast<const ulonglong2*>(sU);

    const int b0 = blockIdx.x * (THREADS * 2) + threadIdx.x;
    const int b1 = b0 + THREADS;
    const float4* in4 = reinterpret_cast<const float4*>(inputs);

    float P0[4], Q0[4], P1[4], Q1[4];
    if (b0 < B) embed_pq(__ldg(in4 + b0), P0, Q0);
    if (b1 < B) embed_pq(__ldg(in4 + b1), P1, Q1);

    unsigned long long y0[N_AMPS], y1[N_AMPS];
    #pragma unroll
    for (int m = 0; m < N_AMPS; m++) { y0[m] = 0ull; y1[m] = 0ull; }

    #pragma unroll
    for (int i = 0; i < N_AMPS; i++) {
        float va = P0[i >> 2] * Q0[i & 3];
        float vb = P1[i >> 2] * Q1[i & 3];
        unsigned long long vp0 = pack2(va, va);
        unsigned long long vp1 = pack2(vb, vb);
        #pragma unroll
        for (int j = 0; j < 8; j++) {
            ulonglong2 uu = sU2[i * 8 + j];     // (U[2j][i], U[2j+1][i])
            asm("fma.rn.f32x2 %0, %1, %2, %0;" : "+l"(y0[2*j    ]) : "l"(uu.x), "l"(vp0));
            asm("fma.rn.f32x2 %0, %1, %2, %0;" : "+l"(y0[2*j + 1]) : "l"(uu.y), "l"(vp0));
            asm("fma.rn.f32x2 %0, %1, %2, %0;" : "+l"(y1[2*j    ]) : "l"(uu.x), "l"(vp1));
            asm("fma.rn.f32x2 %0, %1, %2, %0;" : "+l"(y1[2*j + 1]) : "l"(uu.y), "l"(vp1));
        }
    }

    float4* out4 = reinterpret_cast<float4*>(out);
    if (b0 < B) out4[b0] = readout(y0);
    if (b1 < B) out4[b1] = readout(y1);
}

extern "C" void kernel_launch(void* const* d_in, const int* in_sizes, int n_in,
                              void* d_out, int out_size) {
    const float* inputs  = (const float*)d_in[0];   // (B, 4) float32
    const float* weights = (const float*)d_in[1];   // (6, 4, 3) float32
    float* out = (float*)d_out;                     // (B, 4) float32
    int B = in_sizes[0] / N_QUBITS;

    init_u_kernel<<<1, 256>>>(weights);
    int blocks = (B + THREADS * 2 - 1) / (THREADS * 2);
    quantum_main_kernel<<<blocks, THREADS>>>(inputs, out, B);
}

// round 6
// speedup vs baseline: 1.6658x; 1.1834x over previous
#include <cuda_runtime.h>
#include <cuda_bf16.h>

// 4-qubit circuit, algebraically collapsed:
//   embedded state v = kron of per-wire (cos,sin)  (real)
//   entangling block = fixed 16x16 complex unitary U (weights only)
//   z_w = sign-tree over |U v|^2
//
// R6: R5 minus the spills. launch_bounds(128,4) gives the full 128-reg
// budget (R5's 5-blocks cap at ~100 regs spilled ~20 regs -> alu 12%,
// +3us). First K-step uses mul.rn.f32x2 (no zero-init of accumulators),
// bounds guards dropped (B divisible by 256).

#define N_QUBITS 4
#define N_LAYERS 6
#define N_AMPS   16
#define THREADS  128
#define U_F4     128        // 16x16 complex = 256 float2 = 128 x 16B slots

__device__ float4 g_U[U_F4];   // col i: float2 slots [i*16, i*16+16); m-th = U[m][i]

// ---------------- init: evolve 16 basis columns, shfl pair-exchange ----------------
__global__ void init_u_kernel(const float* __restrict__ w) {
    __shared__ float4 gm[N_LAYERS * N_QUBITS][2];
    int t = threadIdx.x;
    if (t < N_LAYERS * N_QUBITS) {
        float phi   = w[t * 3 + 0];
        float theta = w[t * 3 + 1];
        float omega = w[t * 3 + 2];
        float st, ct, sp, cp, sm, cm;
        __sincosf(theta * 0.5f, &st, &ct);
        __sincosf((phi + omega) * 0.5f, &sp, &cp);
        __sincosf((phi - omega) * 0.5f, &sm, &cm);
        gm[t][0] = make_float4( cp * ct, -sp * ct,   // u00
                               -cm * st, -sm * st);  // u01
        gm[t][1] = make_float4( cm * st, -sm * st,   // u10
                                cp * ct,  sp * ct);  // u11
    }
    __syncthreads();

    // 256 threads = 8 warps; each warp evolves 2 columns (16 lanes each).
    int lane   = t & 31;
    int lane16 = lane & 15;
    int col    = (t >> 5) * 2 + (lane >> 4);
    float re = (lane16 == col) ? 1.0f : 0.0f;
    float im = 0.0f;

    #pragma unroll
    for (int l = 0; l < N_LAYERS; l++) {
        #pragma unroll
        for (int q = 0; q < N_QUBITS; q++) {
            int idx = l * N_QUBITS + q;
            float4 row0 = gm[idx][0];
            float4 row1 = gm[idx][1];
            const int stride = 8 >> q;
            int bit = lane16 & stride;
            float pre = __shfl_xor_sync(0xffffffffu, re, stride);
            float pim = __shfl_xor_sync(0xffffffffu, im, stride);
            float c0r = bit ? row1.x : row0.x,  c0i = bit ? row1.y : row0.y;
            float c1r = bit ? row1.z : row0.z,  c1i = bit ? row1.w : row0.w;
            float a0r = bit ? pre : re,  a0i = bit ? pim : im;
            float a1r = bit ? re : pre,  a1i = bit ? im : pim;
            float nre = c0r * a0r - c0i * a0i + c1r * a1r - c1i * a1i;
            float nim = c0r * a0i + c0i * a0r + c1r * a1i + c1i * a1r;
            re = nre; im = nim;
        }
        const int r = l % (N_QUBITS - 1) + 1;
        #pragma unroll
        for (int q = 0; q < N_QUBITS; q++) {
            const int cbit = 8 >> q, tbit = 8 >> ((q + r) % N_QUBITS);
            float pre = __shfl_xor_sync(0xffffffffu, re, tbit);
            float pim = __shfl_xor_sync(0xffffffffu, im, tbit);
            bool flip = (lane16 & cbit) != 0;
            re = flip ? pre : re;
            im = flip ? pim : im;
        }
    }
    float2* U = reinterpret_cast<float2*>(g_U);
    U[col * N_AMPS + lane16] = make_float2(re, im);
}

// ---------------- main ----------------
__device__ __forceinline__ unsigned long long pack2(float lo, float hi) {
    unsigned long long r;
    asm("mov.b64 %0, {%1, %2};" : "=l"(r) : "f"(lo), "f"(hi));
    return r;
}

__device__ __forceinline__ float4 readout(const unsigned long long* y) {
    float p[N_AMPS];
    #pragma unroll
    for (int m = 0; m < N_AMPS; m++) {
        float re, im;
        asm("mov.b64 {%0, %1}, %2;" : "=f"(re), "=f"(im) : "l"(y[m]));
        p[m] = re * re + im * im;
    }
    float a0 = p[0]  + p[1],  a1 = p[2]  + p[3],  a2 = p[4]  + p[5],  a3 = p[6]  + p[7];
    float a4 = p[8]  + p[9],  a5 = p[10] + p[11], a6 = p[12] + p[13], a7 = p[14] + p[15];
    float z3 = ((p[0] - p[1]) + (p[2] - p[3])) + ((p[4] - p[5]) + (p[6] - p[7]))
             + ((p[8] - p[9]) + (p[10] - p[11])) + ((p[12] - p[13]) + (p[14] - p[15]));
    float b0 = a0 + a1, b1 = a2 + a3, b2 = a4 + a5, b3 = a6 + a7;
    float z2 = ((a0 - a1) + (a2 - a3)) + ((a4 - a5) + (a6 - a7));
    float z1 = (b0 - b1) + (b2 - b3);
    float z0 = (b0 + b1) - (b2 + b3);
    return make_float4(z0, z1, z2, z3);
}

__device__ __forceinline__ void embed_pq(const float4 x, float* P, float* Q) {
    float c0, s0, c1, s1, c2, s2, c3, s3;
    __sincosf(x.x * 0.5f, &s0, &c0);
    __sincosf(x.y * 0.5f, &s1, &c1);
    __sincosf(x.z * 0.5f, &s2, &c2);
    __sincosf(x.w * 0.5f, &s3, &c3);
    P[0] = c0 * c1; P[1] = c0 * s1; P[2] = s0 * c1; P[3] = s0 * s1;
    Q[0] = c2 * c3; Q[1] = c2 * s3; Q[2] = s2 * c3; Q[3] = s2 * s3;
}

__global__ void __launch_bounds__(THREADS, 4)
quantum_main_kernel(const float* __restrict__ inputs,
                    float* __restrict__ out) {
    __shared__ float4 sU[U_F4];
    sU[threadIdx.x] = g_U[threadIdx.x];     // THREADS == U_F4
    __syncthreads();
    const ulonglong2* sU2 = reinterpret_cast<const ulonglong2*>(sU);

    const int b0 = blockIdx.x * (THREADS * 2) + threadIdx.x;
    const int b1 = b0 + THREADS;
    const float4* in4 = reinterpret_cast<const float4*>(inputs);

    float P0[4], Q0[4], P1[4], Q1[4];
    embed_pq(__ldg(in4 + b0), P0, Q0);
    embed_pq(__ldg(in4 + b1), P1, Q1);

    unsigned long long y0[N_AMPS], y1[N_AMPS];

    // ---- i = 0: initialize accumulators with a packed MUL ----
    {
        float va = P0[0] * Q0[0];
        float vb = P1[0] * Q1[0];
        unsigned long long vp0 = pack2(va, va);
        unsigned long long vp1 = pack2(vb, vb);
        #pragma unroll
        for (int j = 0; j < 8; j++) {
            ulonglong2 uu = sU2[j];
            asm("mul.rn.f32x2 %0, %1, %2;" : "=l"(y0[2*j    ]) : "l"(uu.x), "l"(vp0));
            asm("mul.rn.f32x2 %0, %1, %2;" : "=l"(y0[2*j + 1]) : "l"(uu.y), "l"(vp0));
            asm("mul.rn.f32x2 %0, %1, %2;" : "=l"(y1[2*j    ]) : "l"(uu.x), "l"(vp1));
            asm("mul.rn.f32x2 %0, %1, %2;" : "=l"(y1[2*j + 1]) : "l"(uu.y), "l"(vp1));
        }
    }

    // ---- i = 1..15: packed FFMA accumulate ----
    #pragma unroll
    for (int i = 1; i < N_AMPS; i++) {
        float va = P0[i >> 2] * Q0[i & 3];
        float vb = P1[i >> 2] * Q1[i & 3];
        unsigned long long vp0 = pack2(va, va);
        unsigned long long vp1 = pack2(vb, vb);
        #pragma unroll
        for (int j = 0; j < 8; j++) {
            ulonglong2 uu = sU2[i * 8 + j];
            asm("fma.rn.f32x2 %0, %1, %2, %0;" : "+l"(y0[2*j    ]) : "l"(uu.x), "l"(vp0));
            asm("fma.rn.f32x2 %0, %1, %2, %0;" : "+l"(y0[2*j + 1]) : "l"(uu.y), "l"(vp0));
            asm("fma.rn.f32x2 %0, %1, %2, %0;" : "+l"(y1[2*j    ]) : "l"(uu.x), "l"(vp1));
            asm("fma.rn.f32x2 %0, %1, %2, %0;" : "+l"(y1[2*j + 1]) : "l"(uu.y), "l"(vp1));
        }
    }

    float4* out4 = reinterpret_cast<float4*>(out);
    out4[b0] = readout(y0);
    out4[b1] = readout(y1);
}

extern "C" void kernel_launch(void* const* d_in, const int* in_sizes, int n_in,
                              void* d_out, int out_size) {
    const float* inputs  = (const float*)d_in[0];   // (B, 4) float32
    const float* weights = (const float*)d_in[1];   // (6, 4, 3) float32
    float* out = (float*)d_out;                     // (B, 4) float32
    int B = in_sizes[0] / N_QUBITS;

    init_u_kernel<<<1, 256>>>(weights);
    int blocks = B / (THREADS * 2);                 // B = 262144 -> 1024 blocks
    quantum_main_kernel<<<blocks, THREADS>>>(inputs, out);
}